// round 5
// baseline (speedup 1.0000x reference)
#include <cuda_runtime.h>
#include <cuda_fp16.h>
#include <cstdint>

#define NN   100000
#define EE   1600000
#define DIN  48
#define DOUT 16
#define DC   32                      // concatenated output dim (mu | logstd)
#define NBLK ((NN + 255) / 256)      // 391 scan blocks

// Scratch (allocation-free contract: __device__ globals).
// INVARIANT: g_cnt is all-zero at entry to kernel_launch (static zero-init;
// k_agg re-zeroes it at the end of every call).
__device__ unsigned int g_cnt[NN];      // in-degree (without self loop)
__device__ unsigned int g_base[NN];     // CSR row start (finalized by k_fin)
__device__ unsigned int g_cur[NN];      // scatter cursor (init = base by k_fin)
__device__ unsigned int g_bsum[NBLK];   // per-block sums for scan
__device__ unsigned int g_boff[NBLK];   // scanned block offsets
__device__ int          g_esrc[EE];     // src indices sorted by dst
__device__ float        g_dinv[NN];
__device__ __align__(128) __half g_y[(size_t)NN * DC];  // dinv*(x@[Wmu|Wls]) fp16; row = 64B

// ---------------------------------------------------------------------------
// 1: in-degree count on dst (4 edges per thread, vectorized index load)
// ---------------------------------------------------------------------------
__global__ void k_count(const int4* __restrict__ dst4) {
    int i = blockIdx.x * blockDim.x + threadIdx.x;   // EE/4 threads
    if (i < EE / 4) {
        int4 d = __ldg(dst4 + i);
        atomicAdd(&g_cnt[d.x], 1u);
        atomicAdd(&g_cnt[d.y], 1u);
        atomicAdd(&g_cnt[d.z], 1u);
        atomicAdd(&g_cnt[d.w], 1u);
    }
}

// ---------------------------------------------------------------------------
// 2a: per-block exclusive scan of g_cnt -> g_base (block-local) + block sums
// ---------------------------------------------------------------------------
__global__ void k_scanA() {
    __shared__ unsigned ws[8];
    int tid = threadIdx.x;                  // 256
    int i = blockIdx.x * 256 + tid;
    unsigned v = (i < NN) ? g_cnt[i] : 0u;
    unsigned xs = v;
    #pragma unroll
    for (int o = 1; o < 32; o <<= 1) {      // warp inclusive scan
        unsigned t = __shfl_up_sync(0xffffffffu, xs, o);
        if ((tid & 31) >= o) xs += t;
    }
    if ((tid & 31) == 31) ws[tid >> 5] = xs;
    __syncthreads();
    if (tid < 32) {
        unsigned w = (tid < 8) ? ws[tid] : 0u;
        #pragma unroll
        for (int o = 1; o < 8; o <<= 1) {
            unsigned t = __shfl_up_sync(0xffffffffu, w, o);
            if (tid >= o) w += t;
        }
        if (tid < 8) ws[tid] = w;           // inclusive over warp sums
    }
    __syncthreads();
    unsigned woff = (tid >> 5) ? ws[(tid >> 5) - 1] : 0u;
    if (i < NN) g_base[i] = xs - v + woff;           // exclusive within block
    if (tid == 255) g_bsum[blockIdx.x] = xs + woff;  // block total
}

// ---------------------------------------------------------------------------
// 2b: scan the 391 block sums (single block, 512 threads, warp shuffles)
// ---------------------------------------------------------------------------
__global__ void k_scanB() {
    __shared__ unsigned ws[16];
    int tid = threadIdx.x;                  // 512
    unsigned v = (tid < NBLK) ? g_bsum[tid] : 0u;
    unsigned xs = v;
    #pragma unroll
    for (int o = 1; o < 32; o <<= 1) {
        unsigned t = __shfl_up_sync(0xffffffffu, xs, o);
        if ((tid & 31) >= o) xs += t;
    }
    if ((tid & 31) == 31) ws[tid >> 5] = xs;
    __syncthreads();
    if (tid < 32) {
        unsigned w = (tid < 16) ? ws[tid] : 0u;
        #pragma unroll
        for (int o = 1; o < 16; o <<= 1) {
            unsigned t = __shfl_up_sync(0xffffffffu, w, o);
            if (tid >= o) w += t;
        }
        if (tid < 16) ws[tid] = w;
    }
    __syncthreads();
    unsigned woff = (tid >> 5) ? ws[(tid >> 5) - 1] : 0u;
    if (tid < NBLK) g_boff[tid] = xs - v + woff;     // exclusive
}

// ---------------------------------------------------------------------------
// 2c: finalize CSR base (add scanned block offsets), init scatter cursor
// ---------------------------------------------------------------------------
__global__ void k_fin() {
    int i = blockIdx.x * blockDim.x + threadIdx.x;
    if (i >= NN) return;
    unsigned fb = g_base[i] + g_boff[i >> 8];
    g_base[i] = fb;
    g_cur[i]  = fb;
}

// ---------------------------------------------------------------------------
// 3: projection y' = dinv * (x @ Wcat) stored fp16; also store dinv.
//    Depends ONLY on g_cnt -> side stream, overlapped with scans + scatter.
//    8 threads per node, each producing 4 of the 32 cols.
// ---------------------------------------------------------------------------
__global__ void k_project(const float* __restrict__ x,
                          const float* __restrict__ Wmu,
                          const float* __restrict__ Wls) {
    __shared__ float sW[DIN][DC];   // 6 KB, concatenated weights, k-major

    int tid = threadIdx.x;  // 256
    for (int i = tid; i < DIN * DOUT; i += blockDim.x) {
        int k = i / DOUT, j = i % DOUT;
        sW[k][j]      = Wmu[i];
        sW[k][j + 16] = Wls[i];
    }
    __syncthreads();

    int g  = blockIdx.x * blockDim.x + tid;
    int n  = g >> 3;            // node
    int j4 = (g & 7) * 4;       // output column group
    if (n >= NN) return;

    float dinv = rsqrtf(1.0f + (float)g_cnt[n]);
    if ((g & 7) == 0) g_dinv[n] = dinv;

    const float* xr = x + (size_t)n * DIN;
    float ax = 0.f, ay = 0.f, az = 0.f, aw = 0.f;
    #pragma unroll
    for (int k = 0; k < DIN; k++) {
        float xv = __ldg(xr + k);         // broadcast across the 8-thread group
        ax += xv * sW[k][j4 + 0];
        ay += xv * sW[k][j4 + 1];
        az += xv * sW[k][j4 + 2];
        aw += xv * sW[k][j4 + 3];
    }
    __half2 h0 = __floats2half2_rn(ax * dinv, ay * dinv);
    __half2 h1 = __floats2half2_rn(az * dinv, aw * dinv);
    uint2 u;
    u.x = *reinterpret_cast<unsigned*>(&h0);
    u.y = *reinterpret_cast<unsigned*>(&h1);
    *((uint2*)(g_y + (size_t)n * DC + j4)) = u;   // 8B store
}

// ---------------------------------------------------------------------------
// 4: counting-sort scatter (2 edges per thread, vectorized index loads)
// ---------------------------------------------------------------------------
__global__ void k_scatter(const int2* __restrict__ src2,
                          const int2* __restrict__ dst2) {
    int i = blockIdx.x * blockDim.x + threadIdx.x;   // EE/2 threads
    if (i >= EE / 2) return;
    int2 s = __ldg(src2 + i);
    int2 d = __ldg(dst2 + i);
    unsigned p0 = atomicAdd(&g_cur[d.x], 1u);
    g_esrc[p0] = s.x;
    unsigned p1 = atomicAdd(&g_cur[d.y], 1u);
    g_esrc[p1] = s.y;
}

// ---------------------------------------------------------------------------
// 5: aggregate, 8 THREADS PER NODE, no atomics, fp16 gathers, fp32 accum.
//    acc = y'[n] (self) + sum over incoming edges y'[src];  out = dinv*acc + b
//    Also restores the g_cnt==0 invariant for the next graph replay.
// ---------------------------------------------------------------------------
__device__ __forceinline__ float4 ld_row4(int node, int t) {
    uint2 u = __ldg((const uint2*)(g_y + (size_t)node * DC) + t);
    __half2 h0 = *reinterpret_cast<__half2*>(&u.x);
    __half2 h1 = *reinterpret_cast<__half2*>(&u.y);
    float2 f0 = __half22float2(h0);
    float2 f1 = __half22float2(h1);
    return make_float4(f0.x, f0.y, f1.x, f1.y);
}

__global__ void k_agg(const float* __restrict__ bmu,
                      const float* __restrict__ bls,
                      float* __restrict__ out) {
    int g = blockIdx.x * blockDim.x + threadIdx.x;
    int n = g >> 3;             // node
    int t = g & 7;              // 4-col slot within the 32-col row
    if (n >= NN) return;

    unsigned start = g_base[n];
    unsigned deg   = g_cnt[n];

    // restore invariant for next replay (all lanes read via the same LDG above)
    __syncwarp(__activemask());
    if (t == 0) g_cnt[n] = 0u;

    float4 acc = ld_row4(n, t);         // self term (already dinv-scaled)
    const int* ep = g_esrc + start;

    unsigned i = 0;
    for (; i + 4 <= deg; i += 4) {                 // 4-way unroll for MLP
        int s0 = __ldg(ep + i), s1 = __ldg(ep + i + 1);
        int s2 = __ldg(ep + i + 2), s3 = __ldg(ep + i + 3);
        float4 v0 = ld_row4(s0, t), v1 = ld_row4(s1, t);
        float4 v2 = ld_row4(s2, t), v3 = ld_row4(s3, t);
        acc.x += (v0.x + v1.x) + (v2.x + v3.x);
        acc.y += (v0.y + v1.y) + (v2.y + v3.y);
        acc.z += (v0.z + v1.z) + (v2.z + v3.z);
        acc.w += (v0.w + v1.w) + (v2.w + v3.w);
    }
    for (; i < deg; i++) {
        float4 v0 = ld_row4(__ldg(ep + i), t);
        acc.x += v0.x;  acc.y += v0.y;  acc.z += v0.z;  acc.w += v0.w;
    }

    float dn = g_dinv[n];
    int col = (t & 3) * 4;
    const float* bp = (t < 4) ? (bmu + col) : (bls + col);
    float4 o = make_float4(acc.x * dn + __ldg(bp + 0),
                           acc.y * dn + __ldg(bp + 1),
                           acc.z * dn + __ldg(bp + 2),
                           acc.w * dn + __ldg(bp + 3));
    float* obase = (t < 4)
        ? (out + (size_t)n * DOUT + col)                       // mu half
        : (out + (size_t)NN * DOUT + (size_t)n * DOUT + col);  // logstd half
    *(float4*)obase = o;
}

// ---------------------------------------------------------------------------
// Host: side stream + events (host objects only; no device allocation).
// Fork after k_count; project overlaps scans + fin + scatter; join before agg.
// ---------------------------------------------------------------------------
static cudaStream_t g_s2 = nullptr;
static cudaEvent_t  g_evFork = nullptr, g_evJoin = nullptr;
static struct StreamInit {
    StreamInit() {
        cudaStreamCreateWithFlags(&g_s2, cudaStreamNonBlocking);
        cudaEventCreateWithFlags(&g_evFork, cudaEventDisableTiming);
        cudaEventCreateWithFlags(&g_evJoin, cudaEventDisableTiming);
    }
} g_streamInit;

extern "C" void kernel_launch(void* const* d_in, const int* in_sizes, int n_in,
                              void* d_out, int out_size) {
    const float* x   = (const float*)d_in[0];
    const int*   ei  = (const int*)  d_in[1];   // (2, E): row 0 = src, row 1 = dst
    const float* bmu = (const float*)d_in[3];
    const float* Wmu = (const float*)d_in[2];
    const float* Wls = (const float*)d_in[4];
    const float* bls = (const float*)d_in[5];
    float* out = (float*)d_out;

    const int* src = ei;
    const int* dst = ei + EE;

    k_count<<<(EE / 4 + 255) / 256, 256>>>((const int4*)dst);

    bool forked = (g_s2 && g_evFork && g_evJoin);
    if (forked) {
        cudaEventRecord(g_evFork, 0);
        cudaStreamWaitEvent(g_s2, g_evFork, 0);
        k_project<<<(NN * 8 + 255) / 256, 256, 0, g_s2>>>(x, Wmu, Wls);
    }
    k_scanA  <<<NBLK, 256>>>();
    k_scanB  <<<1, 512>>>();
    k_fin    <<<(NN + 255) / 256, 256>>>();
    k_scatter<<<(EE / 2 + 255) / 256, 256>>>((const int2*)src, (const int2*)dst);
    if (forked) {
        cudaEventRecord(g_evJoin, g_s2);
        cudaStreamWaitEvent(0, g_evJoin, 0);
    } else {
        k_project<<<(NN * 8 + 255) / 256, 256>>>(x, Wmu, Wls);
    }
    k_agg<<<(NN * 8 + 255) / 256, 256>>>(bmu, bls, out);
}